// round 15
// baseline (speedup 1.0000x reference)
#include <cuda_runtime.h>
#include <cuda_bf16.h>
#include <math.h>
#include <stdint.h>

typedef unsigned long long ull;

#define B_SZ   32
#define NC     62
#define F_     256
#define NE     512
#define NCF    15872          // NC*F_
#define MROWS  1984           // B_SZ*NC
#define MPAD   2048
#define ZROWS  123008         // B_SZ*NC*NC
#define GSIZE  31490048       // ZROWS*F_
#define KS     768            // B-side split K = 3*F_
#define KZ     512            // A-side compact split [hi|lo]

// ---- device scratch ----
__device__ __align__(16) float d_o[MROWS * F_];
__device__ __align__(16) __nv_bfloat16 d_oqs[MPAD * KZ];         // [hi|lo]
__device__ __align__(16) __nv_bfloat16 d_thT[(size_t)NCF * KS];  // theta^T split [hi|hi|lo]
__device__ __align__(16) __nv_bfloat16 d_cbs[NE * KS];           // cb split [hi|hi|lo]
__device__ __align__(16) __nv_bfloat16 d_zs[(size_t)ZROWS * KZ]; // z split [hi|lo]
__device__ float d_z2[ZROWS];
__device__ float d_cbnorm[NE];
__device__ int   d_idx[ZROWS];
__device__ int   d_histb[B_SZ * NE];
__device__ float d_sfac[B_SZ * F_];
__device__ float d_T[B_SZ * NE];
__device__ float d_loss;

__device__ __forceinline__ float elu1(float x) {
    return x > 0.f ? x : (expf(x) - 1.f);
}

#define SWZ(off) ((off) ^ (((off) >> 3) & 0x70))

__device__ __forceinline__ uint32_t smem_u32(const void* p) {
    return (uint32_t)__cvta_generic_to_shared(p);
}
__device__ __forceinline__ void cp_async16(uint32_t saddr, const void* gmem) {
    asm volatile("cp.async.ca.shared.global [%0], [%1], 16;" :: "r"(saddr), "l"(gmem));
}
__device__ __forceinline__ void cp_commit() { asm volatile("cp.async.commit_group;"); }
__device__ __forceinline__ void cp_wait2()  { asm volatile("cp.async.wait_group 2;"); }
__device__ __forceinline__ void cp_wait1()  { asm volatile("cp.async.wait_group 1;"); }
__device__ __forceinline__ void cp_wait0()  { asm volatile("cp.async.wait_group 0;"); }

__device__ __forceinline__ void ldsm4(uint32_t* r, uint32_t addr) {
    asm volatile("ldmatrix.sync.aligned.m8n8.x4.shared.b16 {%0,%1,%2,%3}, [%4];"
                 : "=r"(r[0]), "=r"(r[1]), "=r"(r[2]), "=r"(r[3]) : "r"(addr));
}
__device__ __forceinline__ void mma16816(float* c, const uint32_t* a, const uint32_t* b) {
    asm volatile("mma.sync.aligned.m16n8k16.row.col.f32.bf16.bf16.f32 "
                 "{%0,%1,%2,%3}, {%4,%5,%6,%7}, {%8,%9}, {%0,%1,%2,%3};"
                 : "+f"(c[0]), "+f"(c[1]), "+f"(c[2]), "+f"(c[3])
                 : "r"(a[0]), "r"(a[1]), "r"(a[2]), "r"(a[3]), "r"(b[0]), "r"(b[1]));
}

// ================= small kernels =================
__global__ void init_kernel() {
    int t = threadIdx.x;
    for (int i = t; i < B_SZ * NE; i += blockDim.x) d_histb[i] = 0;
    if (t == 0) d_loss = 0.f;
}

__global__ __launch_bounds__(256) void cbprep_kernel(const float* __restrict__ cb) {
    int k = blockIdx.x, c = threadIdx.x;
    float v = cb[k * F_ + c];
    __nv_bfloat16 h = __float2bfloat16(v);
    __nv_bfloat16 l = __float2bfloat16(v - __bfloat162float(h));
    d_cbs[k * KS + c] = h;
    d_cbs[k * KS + F_ + c] = h;
    d_cbs[k * KS + 2 * F_ + c] = l;
    __shared__ float red[256];
    red[c] = v * v;
    __syncthreads();
    for (int s = 128; s > 0; s >>= 1) {
        if (c < s) red[c] += red[c + s];
        __syncthreads();
    }
    if (c == 0) d_cbnorm[k] = red[0];
}

__global__ __launch_bounds__(256) void a1_kernel(const float* __restrict__ p,
                                                 const float* __restrict__ x,
                                                 const float* __restrict__ bias) {
    int row = blockIdx.x;
    int b = row / NC, i = row - b * NC;
    int c = threadIdx.x;
    __shared__ float sp[NC];
    if (c < NC) sp[c] = p[i * NC + c];
    __syncthreads();
    float a0 = bias[i * F_ + c], a1 = 0.f;
    const float* xb = x + (size_t)b * NC * F_ + c;
#pragma unroll 2
    for (int j = 0; j < NC; j += 2) {
        a0 += sp[j] * xb[j * F_];
        a1 += sp[j + 1] * xb[(j + 1) * F_];
    }
    d_o[row * F_ + c] = a0 + a1;
}

// oq = o @ q : 8 rows/block, prefetched q, fused bf16 split -> d_oqs
__global__ __launch_bounds__(256) void a2_kernel(const float* __restrict__ q) {
    int row0 = blockIdx.x * 8;
    int c = threadIdx.x;
    __shared__ float so[8][F_];
    for (int i = c; i < 8 * F_; i += 256) {
        int r = row0 + (i >> 8);
        so[i >> 8][i & 255] = (r < MROWS) ? d_o[r * F_ + (i & 255)] : 0.f;
    }
    __syncthreads();
    float acc[8];
#pragma unroll
    for (int u = 0; u < 8; u++) acc[u] = 0.f;
#pragma unroll 2
    for (int k = 0; k < F_; k += 8) {
        float qv[8];
#pragma unroll
        for (int u = 0; u < 8; u++) qv[u] = q[(k + u) * F_ + c];
#pragma unroll
        for (int u = 0; u < 8; u++)
#pragma unroll
            for (int r = 0; r < 8; r++) acc[r] += so[r][k + u] * qv[u];
    }
#pragma unroll
    for (int u = 0; u < 8; u++) {
        int r = row0 + u;
        __nv_bfloat16 h = __float2bfloat16(acc[u]);
        __nv_bfloat16 l = __float2bfloat16(acc[u] - __bfloat162float(h));
        d_oqs[r * KZ + c] = h;
        d_oqs[r * KZ + F_ + c] = l;
    }
}

__global__ void transTheta_kernel(const float* __restrict__ theta) {
    __shared__ float tile[32][33];
    int n0 = blockIdx.x * 32, k0 = blockIdx.y * 32;
    for (int i = threadIdx.y; i < 32; i += 8)
        tile[i][threadIdx.x] = theta[(size_t)(k0 + i) * NCF + n0 + threadIdx.x];
    __syncthreads();
    for (int i = threadIdx.y; i < 32; i += 8) {
        int n = n0 + i;
        int k = k0 + threadIdx.x;
        float v = tile[threadIdx.x][i];
        __nv_bfloat16 h = __float2bfloat16(v);
        __nv_bfloat16 l = __float2bfloat16(v - __bfloat162float(h));
        d_thT[(size_t)n * KS + k] = h;
        d_thT[(size_t)n * KS + F_ + k] = h;
        d_thT[(size_t)n * KS + 2 * F_ + k] = l;
    }
}

// ================= HMMA GEMM 1: g = ELU(oq @ theta) =================
// block 128x256 (one j), 8 warps 2x4, warp tile 64x64, K=768, 4-stage cp.async ring
#define GB_SMEM 196608
__global__ __launch_bounds__(256) void gemmB_mma() {
    extern __shared__ __align__(16) char smem[];
    const int t = threadIdx.x;
    const int wid = t >> 5, lane = t & 31;
    const int warpM = wid & 1, warpN = wid >> 1;
    const int j = blockIdx.x, mt = blockIdx.y;
    const uint32_t sbase = smem_u32(smem);

    float acc[4][8][4];
#pragma unroll
    for (int mi = 0; mi < 4; mi++)
#pragma unroll
        for (int ni = 0; ni < 8; ni++)
#pragma unroll
            for (int e = 0; e < 4; e++) acc[mi][ni][e] = 0.f;

    const uint32_t aRowOff = (uint32_t)((warpM * 64 + (lane & 15)) * 128 + (lane >> 4) * 16);
    const uint32_t bRowOff = (uint32_t)((warpN * 64 + ((lane >> 4) << 3) + (lane & 7)) * 128
                                        + ((lane >> 3) & 1) * 16);

    auto issue = [&](int tile) {
        const int st = tile & 3;
        const int ka = (tile < 8 ? tile : tile - 8) * 64;   // A alias [hi|lo] repeat
        const uint32_t sA = sbase + st * 16384;
        const uint32_t sB = sbase + 65536 + st * 32768;
#pragma unroll
        for (int i = 0; i < 4; i++) {
            int id = t + i * 256;
            int r = id >> 3, ch = id & 7;
            uint32_t off = SWZ((uint32_t)(r * 128 + ch * 16));
            cp_async16(sA + off, d_oqs + (size_t)(mt * 128 + r) * KZ + ka + ch * 8);
        }
#pragma unroll
        for (int i = 0; i < 8; i++) {
            int id = t + i * 256;
            int r = id >> 3, ch = id & 7;
            uint32_t off = SWZ((uint32_t)(r * 128 + ch * 16));
            cp_async16(sB + off, d_thT + (size_t)(j * 256 + r) * KS + tile * 64 + ch * 8);
        }
        cp_commit();
    };

    issue(0); issue(1); issue(2);

    for (int kt = 0; kt < 12; kt++) {
        if (kt < 10) cp_wait2();
        else if (kt == 10) cp_wait1();
        else cp_wait0();
        __syncthreads();
        if (kt + 3 < 12) issue(kt + 3);
        const int st = kt & 3;
        const uint32_t sA = sbase + st * 16384;
        const uint32_t sB = sbase + 65536 + st * 32768;
#pragma unroll
        for (int kk = 0; kk < 4; kk++) {
            uint32_t a[4][4];
#pragma unroll
            for (int mi = 0; mi < 4; mi++)
                ldsm4(a[mi], sA + SWZ(aRowOff + (uint32_t)(mi * 2048) + (uint32_t)(kk * 32)));
            uint32_t b[8][2];
#pragma unroll
            for (int pr = 0; pr < 4; pr++) {
                uint32_t r4[4];
                ldsm4(r4, sB + SWZ(bRowOff + (uint32_t)(pr * 2048) + (uint32_t)(kk * 32)));
                b[pr * 2][0] = r4[0]; b[pr * 2][1] = r4[1];
                b[pr * 2 + 1][0] = r4[2]; b[pr * 2 + 1][1] = r4[3];
            }
#pragma unroll
            for (int mi = 0; mi < 4; mi++)
#pragma unroll
                for (int ni = 0; ni < 8; ni++)
                    mma16816(acc[mi][ni], a[mi], b[ni]);
        }
    }

    // epilogue: ELU + bf16 split -> d_zs [hi|lo]
    const int rbase = mt * 128 + warpM * 64;
#pragma unroll
    for (int mi = 0; mi < 4; mi++) {
#pragma unroll
        for (int half = 0; half < 2; half++) {
            int r = rbase + mi * 16 + (lane >> 2) + half * 8;
            if (r < MROWS) {
                size_t zr = ((size_t)r * NC + j) * KZ;
                uint32_t* hiDst = (uint32_t*)(d_zs + zr);
                uint32_t* loDst = (uint32_t*)(d_zs + zr + F_);
#pragma unroll
                for (int ni = 0; ni < 8; ni++) {
                    int c = warpN * 64 + ni * 8 + 2 * (lane & 3);
                    float v0 = elu1(acc[mi][ni][half * 2]);
                    float v1 = elu1(acc[mi][ni][half * 2 + 1]);
                    __nv_bfloat16 h0 = __float2bfloat16(v0);
                    __nv_bfloat16 h1 = __float2bfloat16(v1);
                    __nv_bfloat16 l0 = __float2bfloat16(v0 - __bfloat162float(h0));
                    __nv_bfloat16 l1 = __float2bfloat16(v1 - __bfloat162float(h1));
                    hiDst[c >> 1] = ((uint32_t)__bfloat16_as_ushort(h1) << 16)
                                  | __bfloat16_as_ushort(h0);
                    loDst[c >> 1] = ((uint32_t)__bfloat16_as_ushort(l1) << 16)
                                  | __bfloat16_as_ushort(l0);
                }
            }
        }
    }
}

// ================= convert: L1-normalize + resplit + ||z||^2 =================
__global__ __launch_bounds__(256) void convert_kernel() {
    int bi = blockIdx.x;
    int c = threadIdx.x;
    int lane = c & 31;
    __shared__ float z2s[NC];
    if (c < NC) z2s[c] = 0.f;
    __nv_bfloat16* base = d_zs + (size_t)bi * NC * KZ;
    float s = 0.f;
#pragma unroll 2
    for (int j = 0; j < NC; j++) {
        float h = __bfloat162float(base[j * KZ + c]);
        float l = __bfloat162float(base[j * KZ + F_ + c]);
        s += fabsf(h + l);
    }
    float inv = 1.f / (s + 1e-6f);
    __syncthreads();
#pragma unroll 1
    for (int j = 0; j < NC; j++) {
        float h = __bfloat162float(base[j * KZ + c]);
        float l = __bfloat162float(base[j * KZ + F_ + c]);
        float z = (h + l) * inv;
        float zz = z * z;
#pragma unroll
        for (int sh = 16; sh > 0; sh >>= 1)
            zz += __shfl_xor_sync(0xFFFFFFFFu, zz, sh);
        if (lane == 0) atomicAdd(&z2s[j], zz);
        __nv_bfloat16 zh = __float2bfloat16(z);
        __nv_bfloat16 zl = __float2bfloat16(z - __bfloat162float(zh));
        base[j * KZ + c] = zh;
        base[j * KZ + F_ + c] = zl;
    }
    __syncthreads();
    if (c < NC) d_z2[bi * NC + c] = z2s[c];
}

// ================= HMMA GEMM 2: VQ scores + argmin/loss/hist =================
// block 128 rows x 512 codes (2 chunks of 256), 4-stage ring
#define VQ_SMEM (196608 + 1024 + 2048 + 64)
__global__ __launch_bounds__(256) void vq_mma() {
    extern __shared__ __align__(16) char smem[];
    ull* best = (ull*)(smem + 196608);
    float* cn = (float*)(smem + 196608 + 1024);
    float* redw = (float*)(smem + 196608 + 1024 + 2048);
    const int t = threadIdx.x;
    const int wid = t >> 5, lane = t & 31;
    const int warpM = wid & 1, warpN = wid >> 1;
    const int bm = blockIdx.x * 128;
    const uint32_t sbase = smem_u32(smem);

    if (t < 128) best[t] = 0xFFFFFFFFFFFFFFFFULL;
    for (int i = t; i < NE; i += 256) cn[i] = d_cbnorm[i];
    __syncthreads();

    const uint32_t aRowOff = (uint32_t)((warpM * 64 + (lane & 15)) * 128 + (lane >> 4) * 16);
    const uint32_t bRowOff = (uint32_t)((warpN * 64 + ((lane >> 4) << 3) + (lane & 7)) * 128
                                        + ((lane >> 3) & 1) * 16);

    for (int nc = 0; nc < 2; nc++) {
        float acc[4][8][4];
#pragma unroll
        for (int mi = 0; mi < 4; mi++)
#pragma unroll
            for (int ni = 0; ni < 8; ni++)
#pragma unroll
                for (int e = 0; e < 4; e++) acc[mi][ni][e] = 0.f;

        auto issue = [&](int tile) {
            const int st = tile & 3;
            const int ka = (tile < 8 ? tile : tile - 8) * 64;
            const uint32_t sA = sbase + st * 16384;
            const uint32_t sB = sbase + 65536 + st * 32768;
#pragma unroll
            for (int i = 0; i < 4; i++) {
                int id = t + i * 256;
                int r = id >> 3, ch = id & 7;
                uint32_t off = SWZ((uint32_t)(r * 128 + ch * 16));
                cp_async16(sA + off, d_zs + (size_t)(bm + r) * KZ + ka + ch * 8);
            }
#pragma unroll
            for (int i = 0; i < 8; i++) {
                int id = t + i * 256;
                int r = id >> 3, ch = id & 7;
                uint32_t off = SWZ((uint32_t)(r * 128 + ch * 16));
                cp_async16(sB + off, d_cbs + (size_t)(nc * 256 + r) * KS + tile * 64 + ch * 8);
            }
            cp_commit();
        };

        issue(0); issue(1); issue(2);

        for (int kt = 0; kt < 12; kt++) {
            if (kt < 10) cp_wait2();
            else if (kt == 10) cp_wait1();
            else cp_wait0();
            __syncthreads();
            if (kt + 3 < 12) issue(kt + 3);
            const int st = kt & 3;
            const uint32_t sA = sbase + st * 16384;
            const uint32_t sB = sbase + 65536 + st * 32768;
#pragma unroll
            for (int kk = 0; kk < 4; kk++) {
                uint32_t a[4][4];
#pragma unroll
                for (int mi = 0; mi < 4; mi++)
                    ldsm4(a[mi], sA + SWZ(aRowOff + (uint32_t)(mi * 2048) + (uint32_t)(kk * 32)));
                uint32_t b[8][2];
#pragma unroll
                for (int pr = 0; pr < 4; pr++) {
                    uint32_t r4[4];
                    ldsm4(r4, sB + SWZ(bRowOff + (uint32_t)(pr * 2048) + (uint32_t)(kk * 32)));
                    b[pr * 2][0] = r4[0]; b[pr * 2][1] = r4[1];
                    b[pr * 2 + 1][0] = r4[2]; b[pr * 2 + 1][1] = r4[3];
                }
#pragma unroll
                for (int mi = 0; mi < 4; mi++)
#pragma unroll
                    for (int ni = 0; ni < 8; ni++)
                        mma16816(acc[mi][ni], a[mi], b[ni]);
            }
        }

        // fold chunk into best[] (dist = ||cb||^2 - 2*score; ties -> lowest k)
#pragma unroll
        for (int mi = 0; mi < 4; mi++) {
            int rl = warpM * 64 + mi * 16 + (lane >> 2);
            float dmin0 = 3.402823e38f, dmin1 = 3.402823e38f;
            int k0 = 0, k1 = 0;
#pragma unroll
            for (int ni = 0; ni < 8; ni++) {
                int kb = nc * 256 + warpN * 64 + ni * 8 + 2 * (lane & 3);
                float c0 = cn[kb], c1 = cn[kb + 1];
                float d;
                d = c0 - 2.f * acc[mi][ni][0]; if (d < dmin0) { dmin0 = d; k0 = kb; }
                d = c1 - 2.f * acc[mi][ni][1]; if (d < dmin0) { dmin0 = d; k0 = kb + 1; }
                d = c0 - 2.f * acc[mi][ni][2]; if (d < dmin1) { dmin1 = d; k1 = kb; }
                d = c1 - 2.f * acc[mi][ni][3]; if (d < dmin1) { dmin1 = d; k1 = kb + 1; }
            }
            unsigned u0 = __float_as_uint(dmin0);
            u0 = (u0 & 0x80000000u) ? ~u0 : (u0 | 0x80000000u);
            atomicMin(&best[rl], ((ull)u0 << 32) | (unsigned)k0);
            unsigned u1 = __float_as_uint(dmin1);
            u1 = (u1 & 0x80000000u) ? ~u1 : (u1 | 0x80000000u);
            atomicMin(&best[rl + 8], ((ull)u1 << 32) | (unsigned)k1);
        }
        __syncthreads();
    }

    // winners
    float lossv = 0.f;
    if (t < 128) {
        int r = bm + t;
        ull key = best[t];
        int k = (int)(key & 0xFFFFFFFFULL);
        d_idx[r] = k;
        atomicAdd(&d_histb[(r / (NC * NC)) * NE + k], 1);
        unsigned uu = (unsigned)(key >> 32);
        unsigned orig = (uu & 0x80000000u) ? (uu & 0x7FFFFFFFu) : ~uu;
        lossv = __uint_as_float(orig) + d_z2[r];
#pragma unroll
        for (int sh = 16; sh > 0; sh >>= 1)
            lossv += __shfl_xor_sync(0xFFFFFFFFu, lossv, sh);
        if (lane == 0) redw[wid] = lossv;
    }
    __syncthreads();
    if (t == 0) atomicAdd(&d_loss, redw[0] + redw[1] + redw[2] + redw[3]);
}

// ================= tail kernels =================
__global__ __launch_bounds__(256) void se_kernel(const float* __restrict__ cb,
                                                 const float* __restrict__ w1,
                                                 const float* __restrict__ b1,
                                                 const float* __restrict__ w2,
                                                 const float* __restrict__ b2) {
    int b = blockIdx.x;
    int c = threadIdx.x;
    __shared__ float sraw[F_];
    __shared__ float h[16];
    float acc = 0.f;
#pragma unroll 4
    for (int k = 0; k < NE; k++) {
        int cnt = d_histb[b * NE + k];
        acc += (float)cnt * cb[k * F_ + c];
    }
    sraw[c] = acc * (1.f / (float)(NC * NC));
    __syncthreads();
    if (c < 16) {
        float a = b1[c];
#pragma unroll 8
        for (int i = 0; i < F_; i++) a += sraw[i] * w1[i * 16 + c];
        h[c] = fmaxf(a, 0.f);
    }
    __syncthreads();
    float a2 = b2[c];
#pragma unroll
    for (int r = 0; r < 16; r++) a2 += h[r] * w2[r * F_ + c];
    float sg = 1.f / (1.f + expf(-a2));
    d_sfac[b * F_ + c] = 1.f + sg;
}

__global__ __launch_bounds__(256) void ttab_kernel(const float* __restrict__ cb) {
    int k = blockIdx.x;
    int b = blockIdx.y;
    int c = threadIdx.x;
    __shared__ float red[256];
    float v = cb[k * F_ + c] * d_sfac[b * F_ + c];
    red[c] = elu1(v);
    __syncthreads();
    for (int s = 128; s > 0; s >>= 1) {
        if (c < s) red[c] += red[c + s];
        __syncthreads();
    }
    if (c == 0) d_T[b * NE + k] = red[0];
}

__global__ __launch_bounds__(64) void final_kernel(float* __restrict__ out, int adj_off) {
    int row = blockIdx.x;
    int b = row / NC;
    int j = threadIdx.x;
    __shared__ float u[64];
    __shared__ float red[64];
    float val = 0.f;
    if (j < NC) {
        int k = d_idx[row * NC + j];
        val = elu1(d_T[b * NE + k]);
    }
    u[j] = val;
    red[j] = fabsf(val);
    __syncthreads();
    for (int s = 32; s > 0; s >>= 1) {
        if (j < s) red[j] += red[j + s];
        __syncthreads();
    }
    if (j < NC) out[adj_off + (size_t)row * NC + j] = u[j] / (red[0] + 1e-6f);
}

__global__ __launch_bounds__(512) void scalars_kernel(float* __restrict__ out) {
    int k = threadIdx.x;
    __shared__ float red[NE];
    int cnt = 0;
    for (int b = 0; b < B_SZ; b++) cnt += d_histb[b * NE + k];
    float pr = (float)cnt * (1.f / (float)ZROWS);
    red[k] = pr * logf(pr + 1e-10f);
    __syncthreads();
    for (int s = 256; s > 0; s >>= 1) {
        if (k < s) red[k] += red[k + s];
        __syncthreads();
    }
    if (k == 0) {
        out[0] = 1.25f * d_loss / (float)GSIZE;
        out[1 + ZROWS] = expf(-red[0]);
    }
}

__global__ __launch_bounds__(256) void copycb_kernel(const float* __restrict__ cb,
                                                     float* __restrict__ out) {
    int k = blockIdx.x, c = threadIdx.x;
    out[2 + ZROWS + (size_t)k * F_ + c] = cb[k * F_ + c];
}

extern "C" void kernel_launch(void* const* d_in, const int* in_sizes, int n_in,
                              void* d_out, int out_size) {
    const float* x     = (const float*)d_in[0];
    const float* p     = (const float*)d_in[1];
    const float* bias  = (const float*)d_in[2];
    const float* q     = (const float*)d_in[3];
    const float* theta = (const float*)d_in[4];
    const float* cb    = (const float*)d_in[5];
    const float* w1    = (const float*)d_in[6];
    const float* b1    = (const float*)d_in[7];
    const float* w2    = (const float*)d_in[8];
    const float* b2    = (const float*)d_in[9];
    float* out = (float*)d_out;

    int full = (out_size >= (1 + ZROWS + 1 + NE * F_)) ? 1 : 0;
    int adj_off = full ? 1 : 0;

    cudaFuncSetAttribute(gemmB_mma, cudaFuncAttributeMaxDynamicSharedMemorySize, GB_SMEM);
    cudaFuncSetAttribute(vq_mma, cudaFuncAttributeMaxDynamicSharedMemorySize, VQ_SMEM);

    init_kernel<<<1, 512>>>();
    cbprep_kernel<<<NE, 256>>>(cb);
    a1_kernel<<<MROWS, 256>>>(p, x, bias);
    a2_kernel<<<MPAD / 8, 256>>>(q);
    transTheta_kernel<<<dim3(NCF / 32, F_ / 32), dim3(32, 8)>>>(theta);
    gemmB_mma<<<dim3(NC, MPAD / 128), 256, GB_SMEM>>>();
    convert_kernel<<<MROWS, 256>>>();
    vq_mma<<<ZROWS / 128, 256, VQ_SMEM>>>();
    se_kernel<<<B_SZ, 256>>>(cb, w1, b1, w2, b2);
    ttab_kernel<<<dim3(NE, B_SZ), 256>>>(cb);
    final_kernel<<<MROWS, 64>>>(out, adj_off);
    if (full) {
        scalars_kernel<<<1, 512>>>(out);
        copycb_kernel<<<NE, 256>>>(cb, out);
    }
}

// round 17
// speedup vs baseline: 1.1433x; 1.1433x over previous
#include <cuda_runtime.h>
#include <cuda_bf16.h>
#include <math.h>
#include <stdint.h>

typedef unsigned long long ull;

#define B_SZ   32
#define NC     62
#define F_     256
#define NE     512
#define NCF    15872          // NC*F_
#define MROWS  1984           // B_SZ*NC
#define MPAD   2048
#define ZROWS  123008         // B_SZ*NC*NC
#define GSIZE  31490048       // ZROWS*F_
#define KZ     512            // compact split [hi|lo] (both A and B sides)

// ---- device scratch ----
__device__ __align__(16) float d_o[MROWS * F_];
__device__ __align__(16) __nv_bfloat16 d_oqs[MPAD * KZ];         // [hi|lo]
__device__ __align__(16) __nv_bfloat16 d_thT[(size_t)NCF * KZ];  // theta^T split [hi|lo]
__device__ __align__(16) __nv_bfloat16 d_cbs[NE * KZ];           // cb split [hi|lo]
__device__ __align__(16) __nv_bfloat16 d_zs[(size_t)ZROWS * KZ]; // z split [hi|lo]
__device__ float d_z2[ZROWS];
__device__ float d_cbnorm[NE];
__device__ int   d_idx[ZROWS];
__device__ int   d_histb[B_SZ * NE];
__device__ float d_sfac[B_SZ * F_];
__device__ float d_T[B_SZ * NE];
__device__ float d_loss;

__device__ __forceinline__ float elu1(float x) {
    return x > 0.f ? x : (expf(x) - 1.f);
}

#define SWZ(off) ((off) ^ (((off) >> 3) & 0x70))

__device__ __forceinline__ uint32_t smem_u32(const void* p) {
    return (uint32_t)__cvta_generic_to_shared(p);
}
__device__ __forceinline__ void cp_async16(uint32_t saddr, const void* gmem) {
    asm volatile("cp.async.ca.shared.global [%0], [%1], 16;" :: "r"(saddr), "l"(gmem));
}
__device__ __forceinline__ void cp_commit() { asm volatile("cp.async.commit_group;"); }
__device__ __forceinline__ void cp_wait1()  { asm volatile("cp.async.wait_group 1;"); }
__device__ __forceinline__ void cp_wait0()  { asm volatile("cp.async.wait_group 0;"); }

__device__ __forceinline__ void ldsm4(uint32_t* r, uint32_t addr) {
    asm volatile("ldmatrix.sync.aligned.m8n8.x4.shared.b16 {%0,%1,%2,%3}, [%4];"
                 : "=r"(r[0]), "=r"(r[1]), "=r"(r[2]), "=r"(r[3]) : "r"(addr));
}
__device__ __forceinline__ void mma16816(float* c, const uint32_t* a, const uint32_t* b) {
    asm volatile("mma.sync.aligned.m16n8k16.row.col.f32.bf16.bf16.f32 "
                 "{%0,%1,%2,%3}, {%4,%5,%6,%7}, {%8,%9}, {%0,%1,%2,%3};"
                 : "+f"(c[0]), "+f"(c[1]), "+f"(c[2]), "+f"(c[3])
                 : "r"(a[0]), "r"(a[1]), "r"(a[2]), "r"(a[3]), "r"(b[0]), "r"(b[1]));
}

__device__ __forceinline__ float bflo(uint32_t u) {
    return __bfloat162float(__ushort_as_bfloat16((unsigned short)(u & 0xFFFFu)));
}
__device__ __forceinline__ float bfhi(uint32_t u) {
    return __bfloat162float(__ushort_as_bfloat16((unsigned short)(u >> 16)));
}
__device__ __forceinline__ uint32_t packbf(float a, float b) {   // a->low, b->high
    return ((uint32_t)__bfloat16_as_ushort(__float2bfloat16(b)) << 16)
         | __bfloat16_as_ushort(__float2bfloat16(a));
}

// logical k-tile (0..11) -> physical 64-col offset in [hi|lo] layouts
__device__ __forceinline__ int kaA(int kt) { return (kt < 8 ? kt : kt - 8) * 64; }   // A: hi,lo,hi
__device__ __forceinline__ int kbB(int kt) { return (kt < 4 ? kt : kt - 4) * 64; }   // B: hi,hi,lo

// ================= small kernels =================
__global__ void init_kernel() {
    int t = threadIdx.x;
    for (int i = t; i < B_SZ * NE; i += blockDim.x) d_histb[i] = 0;
    if (t == 0) d_loss = 0.f;
}

__global__ __launch_bounds__(256) void cbprep_kernel(const float* __restrict__ cb) {
    int k = blockIdx.x, c = threadIdx.x;
    float v = cb[k * F_ + c];
    __nv_bfloat16 h = __float2bfloat16(v);
    __nv_bfloat16 l = __float2bfloat16(v - __bfloat162float(h));
    d_cbs[k * KZ + c] = h;
    d_cbs[k * KZ + F_ + c] = l;
    __shared__ float red[256];
    red[c] = v * v;
    __syncthreads();
    for (int s = 128; s > 0; s >>= 1) {
        if (c < s) red[c] += red[c + s];
        __syncthreads();
    }
    if (c == 0) d_cbnorm[k] = red[0];
}

__global__ __launch_bounds__(256) void a1_kernel(const float* __restrict__ p,
                                                 const float* __restrict__ x,
                                                 const float* __restrict__ bias) {
    int row = blockIdx.x;
    int b = row / NC, i = row - b * NC;
    int c = threadIdx.x;
    __shared__ float sp[NC];
    if (c < NC) sp[c] = p[i * NC + c];
    __syncthreads();
    float a0 = bias[i * F_ + c], a1 = 0.f;
    const float* xb = x + (size_t)b * NC * F_ + c;
#pragma unroll 2
    for (int j = 0; j < NC; j += 2) {
        a0 += sp[j] * xb[j * F_];
        a1 += sp[j + 1] * xb[(j + 1) * F_];
    }
    d_o[row * F_ + c] = a0 + a1;
}

// oq = o @ q : 8 rows/block, prefetched q, fused bf16 split -> d_oqs
__global__ __launch_bounds__(256) void a2_kernel(const float* __restrict__ q) {
    int row0 = blockIdx.x * 8;
    int c = threadIdx.x;
    __shared__ float so[8][F_];
    for (int i = c; i < 8 * F_; i += 256) {
        int r = row0 + (i >> 8);
        so[i >> 8][i & 255] = (r < MROWS) ? d_o[r * F_ + (i & 255)] : 0.f;
    }
    __syncthreads();
    float acc[8];
#pragma unroll
    for (int u = 0; u < 8; u++) acc[u] = 0.f;
#pragma unroll 2
    for (int k = 0; k < F_; k += 8) {
        float qv[8];
#pragma unroll
        for (int u = 0; u < 8; u++) qv[u] = q[(k + u) * F_ + c];
#pragma unroll
        for (int u = 0; u < 8; u++)
#pragma unroll
            for (int r = 0; r < 8; r++) acc[r] += so[r][k + u] * qv[u];
    }
#pragma unroll
    for (int u = 0; u < 8; u++) {
        int r = row0 + u;
        __nv_bfloat16 h = __float2bfloat16(acc[u]);
        __nv_bfloat16 l = __float2bfloat16(acc[u] - __bfloat162float(h));
        d_oqs[r * KZ + c] = h;
        d_oqs[r * KZ + F_ + c] = l;
    }
}

__global__ void transTheta_kernel(const float* __restrict__ theta) {
    __shared__ float tile[32][33];
    int n0 = blockIdx.x * 32, k0 = blockIdx.y * 32;
    for (int i = threadIdx.y; i < 32; i += 8)
        tile[i][threadIdx.x] = theta[(size_t)(k0 + i) * NCF + n0 + threadIdx.x];
    __syncthreads();
    for (int i = threadIdx.y; i < 32; i += 8) {
        int n = n0 + i;
        int k = k0 + threadIdx.x;
        float v = tile[threadIdx.x][i];
        __nv_bfloat16 h = __float2bfloat16(v);
        __nv_bfloat16 l = __float2bfloat16(v - __bfloat162float(h));
        d_thT[(size_t)n * KZ + k] = h;
        d_thT[(size_t)n * KZ + F_ + k] = l;
    }
}

// ================= HMMA GEMM 1: g = ELU(oq @ theta) =================
// block 128x256 (one j), 8 warps 2x4, warp tile 64x64, logical K=768, 2-stage
#define GB_SMEM 98304
__global__ __launch_bounds__(256) void gemmB_mma() {
    extern __shared__ __align__(16) char smem[];
    const int t = threadIdx.x;
    const int wid = t >> 5, lane = t & 31;
    const int warpM = wid & 1, warpN = wid >> 1;
    const int mt = blockIdx.x, j = blockIdx.y;   // mt fastest -> consecutive blocks share B tile
    const uint32_t sbase = smem_u32(smem);

    float acc[4][8][4];
#pragma unroll
    for (int mi = 0; mi < 4; mi++)
#pragma unroll
        for (int ni = 0; ni < 8; ni++)
#pragma unroll
            for (int e = 0; e < 4; e++) acc[mi][ni][e] = 0.f;

    const uint32_t aRowOff = (uint32_t)((warpM * 64 + (lane & 15)) * 128 + (lane >> 4) * 16);
    const uint32_t bRowOff = (uint32_t)((warpN * 64 + ((lane >> 4) << 3) + (lane & 7)) * 128
                                        + ((lane >> 3) & 1) * 16);

    // preload kt=0
#pragma unroll
    for (int i = 0; i < 4; i++) {
        int id = t + i * 256;
        int r = id >> 3, ch = id & 7;
        uint32_t off = SWZ((uint32_t)(r * 128 + ch * 16));
        cp_async16(sbase + off, d_oqs + (size_t)(mt * 128 + r) * KZ + ch * 8);
    }
#pragma unroll
    for (int i = 0; i < 8; i++) {
        int id = t + i * 256;
        int r = id >> 3, ch = id & 7;
        uint32_t off = SWZ((uint32_t)(r * 128 + ch * 16));
        cp_async16(sbase + 32768 + off, d_thT + (size_t)(j * 256 + r) * KZ + ch * 8);
    }
    cp_commit();

    for (int kt = 0; kt < 12; kt++) {
        const int cur = kt & 1, nxt = cur ^ 1;
        if (kt < 11) {
            const int ka = kaA(kt + 1), kb = kbB(kt + 1);
#pragma unroll
            for (int i = 0; i < 4; i++) {
                int id = t + i * 256;
                int r = id >> 3, ch = id & 7;
                uint32_t off = SWZ((uint32_t)(r * 128 + ch * 16));
                cp_async16(sbase + nxt * 16384 + off,
                           d_oqs + (size_t)(mt * 128 + r) * KZ + ka + ch * 8);
            }
#pragma unroll
            for (int i = 0; i < 8; i++) {
                int id = t + i * 256;
                int r = id >> 3, ch = id & 7;
                uint32_t off = SWZ((uint32_t)(r * 128 + ch * 16));
                cp_async16(sbase + 32768 + nxt * 32768 + off,
                           d_thT + (size_t)(j * 256 + r) * KZ + kb + ch * 8);
            }
            cp_commit();
            cp_wait1();
        } else {
            cp_wait0();
        }
        __syncthreads();
        const uint32_t sA = sbase + cur * 16384;
        const uint32_t sB = sbase + 32768 + cur * 32768;
#pragma unroll
        for (int kk = 0; kk < 4; kk++) {
            uint32_t a[4][4];
#pragma unroll
            for (int mi = 0; mi < 4; mi++)
                ldsm4(a[mi], sA + SWZ(aRowOff + (uint32_t)(mi * 2048) + (uint32_t)(kk * 32)));
            uint32_t b[8][2];
#pragma unroll
            for (int pr = 0; pr < 4; pr++) {
                uint32_t r4[4];
                ldsm4(r4, sB + SWZ(bRowOff + (uint32_t)(pr * 2048) + (uint32_t)(kk * 32)));
                b[pr * 2][0] = r4[0]; b[pr * 2][1] = r4[1];
                b[pr * 2 + 1][0] = r4[2]; b[pr * 2 + 1][1] = r4[3];
            }
#pragma unroll
            for (int mi = 0; mi < 4; mi++)
#pragma unroll
                for (int ni = 0; ni < 8; ni++)
                    mma16816(acc[mi][ni], a[mi], b[ni]);
        }
        __syncthreads();
    }

    // epilogue: ELU + bf16 split -> d_zs [hi|lo]
    const int rbase = mt * 128 + warpM * 64;
#pragma unroll
    for (int mi = 0; mi < 4; mi++) {
#pragma unroll
        for (int half = 0; half < 2; half++) {
            int r = rbase + mi * 16 + (lane >> 2) + half * 8;
            if (r < MROWS) {
                size_t zr = ((size_t)r * NC + j) * KZ;
                uint32_t* hiDst = (uint32_t*)(d_zs + zr);
                uint32_t* loDst = (uint32_t*)(d_zs + zr + F_);
#pragma unroll
                for (int ni = 0; ni < 8; ni++) {
                    int c = warpN * 64 + ni * 8 + 2 * (lane & 3);
                    float v0 = elu1(acc[mi][ni][half * 2]);
                    float v1 = elu1(acc[mi][ni][half * 2 + 1]);
                    __nv_bfloat16 h0 = __float2bfloat16(v0);
                    __nv_bfloat16 h1 = __float2bfloat16(v1);
                    __nv_bfloat16 l0 = __float2bfloat16(v0 - __bfloat162float(h0));
                    __nv_bfloat16 l1 = __float2bfloat16(v1 - __bfloat162float(h1));
                    hiDst[c >> 1] = ((uint32_t)__bfloat16_as_ushort(h1) << 16)
                                  | __bfloat16_as_ushort(h0);
                    loDst[c >> 1] = ((uint32_t)__bfloat16_as_ushort(l1) << 16)
                                  | __bfloat16_as_ushort(l0);
                }
            }
        }
    }
}

// ================= convert: L1-normalize + resplit + ||z||^2 (warp-per-j, uint4) ====
__global__ __launch_bounds__(256) void convert_kernel() {
    int bi = blockIdx.x;
    const int t = threadIdx.x, w = t >> 5, lane = t & 31;
    __shared__ float sabs[8][256];
    __shared__ float sinv[256];
    __nv_bfloat16* base = d_zs + (size_t)bi * NC * KZ;

    // pass1: per-(warp,c) partial |h+l| sums
    float pa[8];
#pragma unroll
    for (int u = 0; u < 8; u++) pa[u] = 0.f;
    for (int j = w; j < NC; j += 8) {
        const uint4 hv = *reinterpret_cast<const uint4*>(base + j * KZ + lane * 8);
        const uint4 lv = *reinterpret_cast<const uint4*>(base + j * KZ + F_ + lane * 8);
        const uint32_t* hw = (const uint32_t*)&hv;
        const uint32_t* lw = (const uint32_t*)&lv;
#pragma unroll
        for (int u = 0; u < 4; u++) {
            pa[2 * u]     += fabsf(bflo(hw[u]) + bflo(lw[u]));
            pa[2 * u + 1] += fabsf(bfhi(hw[u]) + bfhi(lw[u]));
        }
    }
#pragma unroll
    for (int u = 0; u < 8; u++) sabs[w][lane * 8 + u] = pa[u];
    __syncthreads();

    // pass2: combine
    float s = 0.f;
#pragma unroll
    for (int w2 = 0; w2 < 8; w2++) s += sabs[w2][t];
    sinv[t] = 1.f / (s + 1e-6f);
    __syncthreads();

    // pass3: normalize, resplit, ||z||^2 per j
    for (int j = w; j < NC; j += 8) {
        uint4 hv = *reinterpret_cast<const uint4*>(base + j * KZ + lane * 8);
        uint4 lv = *reinterpret_cast<const uint4*>(base + j * KZ + F_ + lane * 8);
        uint32_t* hw = (uint32_t*)&hv;
        uint32_t* lw = (uint32_t*)&lv;
        float zz = 0.f;
#pragma unroll
        for (int u = 0; u < 4; u++) {
            float z0 = (bflo(hw[u]) + bflo(lw[u])) * sinv[lane * 8 + 2 * u];
            float z1 = (bfhi(hw[u]) + bfhi(lw[u])) * sinv[lane * 8 + 2 * u + 1];
            zz += z0 * z0 + z1 * z1;
            __nv_bfloat16 h0 = __float2bfloat16(z0);
            __nv_bfloat16 h1 = __float2bfloat16(z1);
            float l0 = z0 - __bfloat162float(h0);
            float l1 = z1 - __bfloat162float(h1);
            hw[u] = ((uint32_t)__bfloat16_as_ushort(h1) << 16) | __bfloat16_as_ushort(h0);
            lw[u] = packbf(l0, l1);
        }
        *reinterpret_cast<uint4*>(base + j * KZ + lane * 8) = hv;
        *reinterpret_cast<uint4*>(base + j * KZ + F_ + lane * 8) = lv;
#pragma unroll
        for (int sh = 16; sh > 0; sh >>= 1)
            zz += __shfl_xor_sync(0xFFFFFFFFu, zz, sh);
        if (lane == 0) d_z2[bi * NC + j] = zz;
    }
}

// ================= HMMA GEMM 2: VQ scores + argmin/loss/hist =================
// block 128 rows x 512 codes (2 chunks of 256), 2-stage
#define VQ_SMEM (98304 + 1024 + 2048 + 64)
__global__ __launch_bounds__(256) void vq_mma() {
    extern __shared__ __align__(16) char smem[];
    ull* best = (ull*)(smem + 98304);
    float* cn = (float*)(smem + 98304 + 1024);
    float* redw = (float*)(smem + 98304 + 1024 + 2048);
    const int t = threadIdx.x;
    const int wid = t >> 5, lane = t & 31;
    const int warpM = wid & 1, warpN = wid >> 1;
    const int bm = blockIdx.x * 128;
    const uint32_t sbase = smem_u32(smem);

    if (t < 128) best[t] = 0xFFFFFFFFFFFFFFFFULL;
    for (int i = t; i < NE; i += 256) cn[i] = d_cbnorm[i];
    __syncthreads();

    const uint32_t aRowOff = (uint32_t)((warpM * 64 + (lane & 15)) * 128 + (lane >> 4) * 16);
    const uint32_t bRowOff = (uint32_t)((warpN * 64 + ((lane >> 4) << 3) + (lane & 7)) * 128
                                        + ((lane >> 3) & 1) * 16);

    for (int nc = 0; nc < 2; nc++) {
        float acc[4][8][4];
#pragma unroll
        for (int mi = 0; mi < 4; mi++)
#pragma unroll
            for (int ni = 0; ni < 8; ni++)
#pragma unroll
                for (int e = 0; e < 4; e++) acc[mi][ni][e] = 0.f;

        // preload kt=0
#pragma unroll
        for (int i = 0; i < 4; i++) {
            int id = t + i * 256;
            int r = id >> 3, ch = id & 7;
            uint32_t off = SWZ((uint32_t)(r * 128 + ch * 16));
            cp_async16(sbase + off, d_zs + (size_t)(bm + r) * KZ + ch * 8);
        }
#pragma unroll
        for (int i = 0; i < 8; i++) {
            int id = t + i * 256;
            int r = id >> 3, ch = id & 7;
            uint32_t off = SWZ((uint32_t)(r * 128 + ch * 16));
            cp_async16(sbase + 32768 + off, d_cbs + (size_t)(nc * 256 + r) * KZ + ch * 8);
        }
        cp_commit();

        for (int kt = 0; kt < 12; kt++) {
            const int cur = kt & 1, nxt = cur ^ 1;
            if (kt < 11) {
                const int ka = kaA(kt + 1), kb = kbB(kt + 1);
#pragma unroll
                for (int i = 0; i < 4; i++) {
                    int id = t + i * 256;
                    int r = id >> 3, ch = id & 7;
                    uint32_t off = SWZ((uint32_t)(r * 128 + ch * 16));
                    cp_async16(sbase + nxt * 16384 + off,
                               d_zs + (size_t)(bm + r) * KZ + ka + ch * 8);
                }
#pragma unroll
                for (int i = 0; i < 8; i++) {
                    int id = t + i * 256;
                    int r = id >> 3, ch = id & 7;
                    uint32_t off = SWZ((uint32_t)(r * 128 + ch * 16));
                    cp_async16(sbase + 32768 + nxt * 32768 + off,
                               d_cbs + (size_t)(nc * 256 + r) * KZ + kb + ch * 8);
                }
                cp_commit();
                cp_wait1();
            } else {
                cp_wait0();
            }
            __syncthreads();
            const uint32_t sA = sbase + cur * 16384;
            const uint32_t sB = sbase + 32768 + cur * 32768;
#pragma unroll
            for (int kk = 0; kk < 4; kk++) {
                uint32_t a[4][4];
#pragma unroll
                for (int mi = 0; mi < 4; mi++)
                    ldsm4(a[mi], sA + SWZ(aRowOff + (uint32_t)(mi * 2048) + (uint32_t)(kk * 32)));
                uint32_t b[8][2];
#pragma unroll
                for (int pr = 0; pr < 4; pr++) {
                    uint32_t r4[4];
                    ldsm4(r4, sB + SWZ(bRowOff + (uint32_t)(pr * 2048) + (uint32_t)(kk * 32)));
                    b[pr * 2][0] = r4[0]; b[pr * 2][1] = r4[1];
                    b[pr * 2 + 1][0] = r4[2]; b[pr * 2 + 1][1] = r4[3];
                }
#pragma unroll
                for (int mi = 0; mi < 4; mi++)
#pragma unroll
                    for (int ni = 0; ni < 8; ni++)
                        mma16816(acc[mi][ni], a[mi], b[ni]);
            }
            __syncthreads();
        }

        // fold chunk into best[] (dist = ||cb||^2 - 2*score; ties -> lowest k)
#pragma unroll
        for (int mi = 0; mi < 4; mi++) {
            int rl = warpM * 64 + mi * 16 + (lane >> 2);
            float dmin0 = 3.402823e38f, dmin1 = 3.402823e38f;
            int k0 = 0, k1 = 0;
#pragma unroll
            for (int ni = 0; ni < 8; ni++) {
                int kb = nc * 256 + warpN * 64 + ni * 8 + 2 * (lane & 3);
                float c0 = cn[kb], c1 = cn[kb + 1];
                float d;
                d = c0 - 2.f * acc[mi][ni][0]; if (d < dmin0) { dmin0 = d; k0 = kb; }
                d = c1 - 2.f * acc[mi][ni][1]; if (d < dmin0) { dmin0 = d; k0 = kb + 1; }
                d = c0 - 2.f * acc[mi][ni][2]; if (d < dmin1) { dmin1 = d; k1 = kb; }
                d = c1 - 2.f * acc[mi][ni][3]; if (d < dmin1) { dmin1 = d; k1 = kb + 1; }
            }
            unsigned u0 = __float_as_uint(dmin0);
            u0 = (u0 & 0x80000000u) ? ~u0 : (u0 | 0x80000000u);
            atomicMin(&best[rl], ((ull)u0 << 32) | (unsigned)k0);
            unsigned u1 = __float_as_uint(dmin1);
            u1 = (u1 & 0x80000000u) ? ~u1 : (u1 | 0x80000000u);
            atomicMin(&best[rl + 8], ((ull)u1 << 32) | (unsigned)k1);
        }
        __syncthreads();
    }

    // winners
    float lossv = 0.f;
    if (t < 128) {
        int r = bm + t;
        ull key = best[t];
        int k = (int)(key & 0xFFFFFFFFULL);
        d_idx[r] = k;
        atomicAdd(&d_histb[(r / (NC * NC)) * NE + k], 1);
        unsigned uu = (unsigned)(key >> 32);
        unsigned orig = (uu & 0x80000000u) ? (uu & 0x7FFFFFFFu) : ~uu;
        lossv = __uint_as_float(orig) + d_z2[r];
#pragma unroll
        for (int sh = 16; sh > 0; sh >>= 1)
            lossv += __shfl_xor_sync(0xFFFFFFFFu, lossv, sh);
        if (lane == 0) redw[wid] = lossv;
    }
    __syncthreads();
    if (t == 0) atomicAdd(&d_loss, redw[0] + redw[1] + redw[2] + redw[3]);
}

// ================= tail kernels =================
__global__ __launch_bounds__(256) void se_kernel(const float* __restrict__ cb,
                                                 const float* __restrict__ w1,
                                                 const float* __restrict__ b1,
                                                 const float* __restrict__ w2,
                                                 const float* __restrict__ b2) {
    int b = blockIdx.x;
    int c = threadIdx.x;
    __shared__ float sraw[F_];
    __shared__ float h[16];
    float acc = 0.f;
#pragma unroll 4
    for (int k = 0; k < NE; k++) {
        int cnt = d_histb[b * NE + k];
        acc += (float)cnt * cb[k * F_ + c];
    }
    sraw[c] = acc * (1.f / (float)(NC * NC));
    __syncthreads();
    if (c < 16) {
        float a = b1[c];
#pragma unroll 8
        for (int i = 0; i < F_; i++) a += sraw[i] * w1[i * 16 + c];
        h[c] = fmaxf(a, 0.f);
    }
    __syncthreads();
    float a2 = b2[c];
#pragma unroll
    for (int r = 0; r < 16; r++) a2 += h[r] * w2[r * F_ + c];
    float sg = 1.f / (1.f + expf(-a2));
    d_sfac[b * F_ + c] = 1.f + sg;
}

__global__ __launch_bounds__(256) void ttab_kernel(const float* __restrict__ cb) {
    int k = blockIdx.x;
    int b = blockIdx.y;
    int c = threadIdx.x;
    __shared__ float red[256];
    float v = cb[k * F_ + c] * d_sfac[b * F_ + c];
    red[c] = elu1(v);
    __syncthreads();
    for (int s = 128; s > 0; s >>= 1) {
        if (c < s) red[c] += red[c + s];
        __syncthreads();
    }
    if (c == 0) d_T[b * NE + k] = red[0];
}

__global__ __launch_bounds__(64) void final_kernel(float* __restrict__ out, int adj_off) {
    int row = blockIdx.x;
    int b = row / NC;
    int j = threadIdx.x;
    __shared__ float u[64];
    __shared__ float red[64];
    float val = 0.f;
    if (j < NC) {
        int k = d_idx[row * NC + j];
        val = elu1(d_T[b * NE + k]);
    }
    u[j] = val;
    red[j] = fabsf(val);
    __syncthreads();
    for (int s = 32; s > 0; s >>= 1) {
        if (j < s) red[j] += red[j + s];
        __syncthreads();
    }
    if (j < NC) out[adj_off + (size_t)row * NC + j] = u[j] / (red[0] + 1e-6f);
}

__global__ __launch_bounds__(512) void scalars_kernel(float* __restrict__ out) {
    int k = threadIdx.x;
    __shared__ float red[NE];
    int cnt = 0;
    for (int b = 0; b < B_SZ; b++) cnt += d_histb[b * NE + k];
    float pr = (float)cnt * (1.f / (float)ZROWS);
    red[k] = pr * logf(pr + 1e-10f);
    __syncthreads();
    for (int s = 256; s > 0; s >>= 1) {
        if (k < s) red[k] += red[k + s];
        __syncthreads();
    }
    if (k == 0) {
        out[0] = 1.25f * d_loss / (float)GSIZE;
        out[1 + ZROWS] = expf(-red[0]);
    }
}

__global__ __launch_bounds__(256) void copycb_kernel(const float* __restrict__ cb,
                                                     float* __restrict__ out) {
    int k = blockIdx.x, c = threadIdx.x;
    out[2 + ZROWS + (size_t)k * F_ + c] = cb[k * F_ + c];
}

extern "C" void kernel_launch(void* const* d_in, const int* in_sizes, int n_in,
                              void* d_out, int out_size) {
    const float* x     = (const float*)d_in[0];
    const float* p     = (const float*)d_in[1];
    const float* bias  = (const float*)d_in[2];
    const float* q     = (const float*)d_in[3];
    const float* theta = (const float*)d_in[4];
    const float* cb    = (const float*)d_in[5];
    const float* w1    = (const float*)d_in[6];
    const float* b1    = (const float*)d_in[7];
    const float* w2    = (const float*)d_in[8];
    const float* b2    = (const float*)d_in[9];
    float* out = (float*)d_out;

    int full = (out_size >= (1 + ZROWS + 1 + NE * F_)) ? 1 : 0;
    int adj_off = full ? 1 : 0;

    cudaFuncSetAttribute(gemmB_mma, cudaFuncAttributeMaxDynamicSharedMemorySize, GB_SMEM);
    cudaFuncSetAttribute(vq_mma, cudaFuncAttributeMaxDynamicSharedMemorySize, VQ_SMEM);

    init_kernel<<<1, 512>>>();
    cbprep_kernel<<<NE, 256>>>(cb);
    a1_kernel<<<MROWS, 256>>>(p, x, bias);
    a2_kernel<<<MPAD / 8, 256>>>(q);
    transTheta_kernel<<<dim3(NCF / 32, F_ / 32), dim3(32, 8)>>>(theta);
    gemmB_mma<<<dim3(MPAD / 128, NC), 256, GB_SMEM>>>();
    convert_kernel<<<MROWS, 256>>>();
    vq_mma<<<ZROWS / 128, 256, VQ_SMEM>>>();
    se_kernel<<<B_SZ, 256>>>(cb, w1, b1, w2, b2);
    ttab_kernel<<<dim3(NE, B_SZ), 256>>>(cb);
    final_kernel<<<MROWS, 64>>>(out, adj_off);
    if (full) {
        scalars_kernel<<<1, 512>>>(out);
        copycb_kernel<<<NE, 256>>>(cb, out);
    }
}